// round 16
// baseline (speedup 1.0000x reference)
#include <cuda_runtime.h>
#include <cstddef>

#define NN 100000
#define NE 3200000
#define FIN 512
#define HID 64
#define NC  64
#define KHOPS 20
#define PAD 128            // edge slots per node (max deg ~70 for Poisson(32))

// ---------------- scratch (device globals; no allocation allowed) ------------
__device__ float g_xL[(size_t)NN * NC];          // fp32 logits (hop-0 input)
__device__ float g_xA[(size_t)NN * NC];          // ping
__device__ float g_xB[(size_t)NN * NC];          // pong
__device__ int   g_cnt[NN];                      // zero at load; last hop self-clears
__device__ int2  g_edges[(size_t)NN * PAD];      // bucketed (sender*16, weight-bits)

// ---------------- bucketed scatter (no hist/scan needed) ---------------------
__global__ void k_scatter(const int* __restrict__ snd, const int* __restrict__ rcv,
                          const float* __restrict__ w) {
    int e = blockIdx.x * blockDim.x + threadIdx.x;
    if (e >= NE) return;
    int r = rcv[e];
    int pos = atomicAdd(&g_cnt[r], 1);
    if (pos < PAD)   // memory-safety clamp; statistically never taken
        g_edges[(size_t)r * PAD + pos] = make_int2(snd[e] * 16, __float_as_int(w[e]));
}

// ------ fused MLP: logits = relu(X@W1+b1)@W2+b2 -> xL; hop-0 gate -> out -----
__global__ __launch_bounds__(256) void k_mlp(const float* __restrict__ A,
                                             const float* __restrict__ W1,
                                             const float* __restrict__ b1,
                                             const float* __restrict__ W2,
                                             const float* __restrict__ b2,
                                             const float* __restrict__ Wg,
                                             const float* __restrict__ bg,
                                             float* __restrict__ XL,
                                             float* __restrict__ out, int M) {
    constexpr int BM = 128, BK = 16;
    __shared__ float Hs[HID][BM + 4];      // hidden tile (persists to phase 2)
    __shared__ float Ts[BK][BM + 4];       // phase1: X tile; phase2: aliased W2 chunk
    __shared__ float Ws[BK][HID];          // phase1: W1 tile

    const int tid = threadIdx.x;
    const int block_row = blockIdx.x * BM;
    const int tx = tid & 15;               // 16 col-groups of 4
    const int ty = tid >> 4;               // 16 row-groups of 8

    const int ar = tid >> 2;
    const int ac = (tid & 3) << 2;
    const int br = tid >> 4;
    const int bc = (tid & 15) << 2;

    // ---------- phase 1: h = relu(X@W1+b1), kept in SMEM ----------
    float acc[8][4];
#pragma unroll
    for (int i = 0; i < 8; ++i)
#pragma unroll
        for (int j = 0; j < 4; ++j) acc[i][j] = 0.f;

    for (int k0 = 0; k0 < FIN; k0 += BK) {
#pragma unroll
        for (int i = 0; i < 2; ++i) {
            int row = block_row + ar + i * 64;
            float4 v = make_float4(0.f, 0.f, 0.f, 0.f);
            if (row < M) v = *(const float4*)(A + (size_t)row * FIN + k0 + ac);
            Ts[ac + 0][ar + i * 64] = v.x;
            Ts[ac + 1][ar + i * 64] = v.y;
            Ts[ac + 2][ar + i * 64] = v.z;
            Ts[ac + 3][ar + i * 64] = v.w;
        }
        *(float4*)&Ws[br][bc] = *(const float4*)(W1 + (size_t)(k0 + br) * HID + bc);
        __syncthreads();
#pragma unroll
        for (int kk = 0; kk < BK; ++kk) {
            float4 a0 = *(const float4*)&Ts[kk][ty * 8 + 0];
            float4 a1 = *(const float4*)&Ts[kk][ty * 8 + 4];
            float4 b0 = *(const float4*)&Ws[kk][tx * 4];
            float a[8] = {a0.x, a0.y, a0.z, a0.w, a1.x, a1.y, a1.z, a1.w};
            float b[4] = {b0.x, b0.y, b0.z, b0.w};
#pragma unroll
            for (int i = 0; i < 8; ++i)
#pragma unroll
                for (int j = 0; j < 4; ++j) acc[i][j] += a[i] * b[j];
        }
        __syncthreads();
    }
#pragma unroll
    for (int i = 0; i < 8; ++i)
#pragma unroll
        for (int j = 0; j < 4; ++j)
            Hs[tx * 4 + j][ty * 8 + i] = fmaxf(acc[i][j] + b1[tx * 4 + j], 0.f);
    __syncthreads();

    // ---------- phase 2: logits = h@W2+b2 (W2 in 2 chunks aliasing Ts) ----------
    float* W2c = &Ts[0][0];
    float acc2[8][4];
#pragma unroll
    for (int i = 0; i < 8; ++i)
#pragma unroll
        for (int j = 0; j < 4; ++j) acc2[i][j] = 0.f;

#pragma unroll
    for (int half = 0; half < 2; ++half) {
        {
            int base = tid * 8;
            const float* src = W2 + (size_t)(half * 32) * HID;
#pragma unroll
            for (int u = 0; u < 2; ++u)
                *(float4*)&W2c[base + u * 4] = *(const float4*)(src + base + u * 4);
        }
        __syncthreads();
#pragma unroll
        for (int kk = 0; kk < 32; ++kk) {
            float4 a0 = *(const float4*)&Hs[half * 32 + kk][ty * 8 + 0];
            float4 a1 = *(const float4*)&Hs[half * 32 + kk][ty * 8 + 4];
            float4 b0 = *(const float4*)&W2c[kk * HID + tx * 4];
            float a[8] = {a0.x, a0.y, a0.z, a0.w, a1.x, a1.y, a1.z, a1.w};
            float b[4] = {b0.x, b0.y, b0.z, b0.w};
#pragma unroll
            for (int i = 0; i < 8; ++i)
#pragma unroll
                for (int j = 0; j < 4; ++j) acc2[i][j] += a[i] * b[j];
        }
        __syncthreads();
    }

    // ---------- epilogue: bias + hop-0 gate ----------
    float wgl[4];
#pragma unroll
    for (int j = 0; j < 4; ++j) wgl[j] = Wg[tx * 4 + j];
    float bgl = bg[0];
#pragma unroll
    for (int i = 0; i < 8; ++i) {
        float v0 = acc2[i][0] + b2[tx * 4 + 0];
        float v1 = acc2[i][1] + b2[tx * 4 + 1];
        float v2 = acc2[i][2] + b2[tx * 4 + 2];
        float v3 = acc2[i][3] + b2[tx * 4 + 3];
        float part = v0 * wgl[0] + v1 * wgl[1] + v2 * wgl[2] + v3 * wgl[3];
#pragma unroll
        for (int o = 8; o; o >>= 1) part += __shfl_xor_sync(0xffffffffu, part, o);
        float gsc = 1.f / (1.f + __expf(-(part + bgl)));
        int row = block_row + ty * 8 + i;
        if (row < M) {
            *(float4*)(XL + (size_t)row * NC + tx * 4) = make_float4(v0, v1, v2, v3);
            float4 o4 = make_float4(gsc * v0, gsc * v1, gsc * v2, gsc * v3);
            *(float4*)(out + (size_t)row * NC + tx * 4) = o4;
        }
    }
}

// ---- SpMM hop: float4 lanes, 2 edges per gather instruction, fused gate -----
__global__ __launch_bounds__(256) void k_spmm_gate(const float* __restrict__ xin,
                                                   float* __restrict__ yout,
                                                   int store_y, int clear,
                                                   const float* __restrict__ Wg,
                                                   const float* __restrict__ bg,
                                                   float* __restrict__ out) {
    int gw = (blockIdx.x * blockDim.x + threadIdx.x) >> 5;  // node; NN = 12500*8
    int lane = threadIdx.x & 31;
    const int half = lane >> 4;        // 0: edge A, 1: edge B
    const int l15  = lane & 15;        // float4 slot within row (channels l15*4..+3)
    const float4* __restrict__ x4 = (const float4*)xin;

    const int cnt = g_cnt[gw];
    const int2* eb  = g_edges + (size_t)gw * PAD;           // 1KB-aligned segment
    const int4* ebp = (const int4*)eb;                      // edge pairs

    float4 acc = make_float4(0.f, 0.f, 0.f, 0.f);

    const int npairs = cnt >> 1;
    int i = 0;
    for (; i + 4 <= npairs; i += 4) {                       // 8 edges, 4 gather LDG.128
        int4 p0 = ebp[i + 0];
        int4 p1 = ebp[i + 1];
        int4 p2 = ebp[i + 2];
        int4 p3 = ebp[i + 3];
        int   s0 = half ? p0.z : p0.x;
        int   s1 = half ? p1.z : p1.x;
        int   s2 = half ? p2.z : p2.x;
        int   s3 = half ? p3.z : p3.x;
        float w0 = __int_as_float(half ? p0.w : p0.y);
        float w1 = __int_as_float(half ? p1.w : p1.y);
        float w2 = __int_as_float(half ? p2.w : p2.y);
        float w3 = __int_as_float(half ? p3.w : p3.y);
        float4 v0 = x4[s0 + l15];                           // s pre-multiplied by 16
        float4 v1 = x4[s1 + l15];
        float4 v2 = x4[s2 + l15];
        float4 v3 = x4[s3 + l15];
        acc.x += w0 * v0.x; acc.y += w0 * v0.y; acc.z += w0 * v0.z; acc.w += w0 * v0.w;
        acc.x += w1 * v1.x; acc.y += w1 * v1.y; acc.z += w1 * v1.z; acc.w += w1 * v1.w;
        acc.x += w2 * v2.x; acc.y += w2 * v2.y; acc.z += w2 * v2.z; acc.w += w2 * v2.w;
        acc.x += w3 * v3.x; acc.y += w3 * v3.y; acc.z += w3 * v3.z; acc.w += w3 * v3.w;
    }
    for (; i < npairs; ++i) {
        int4 p = ebp[i];
        int   s = half ? p.z : p.x;
        float w = __int_as_float(half ? p.w : p.y);
        float4 v = x4[s + l15];
        acc.x += w * v.x; acc.y += w * v.y; acc.z += w * v.z; acc.w += w * v.w;
    }
    if (cnt & 1) {                                          // odd leftover: half 0 only
        int2 ep = eb[cnt - 1];
        if (half == 0) {
            float w = __int_as_float(ep.y);
            float4 v = x4[ep.x + l15];
            acc.x += w * v.x; acc.y += w * v.y; acc.z += w * v.z; acc.w += w * v.w;
        }
    }

    // fold the two half-warps (edge-A sums + edge-B sums)
    acc.x += __shfl_xor_sync(0xffffffffu, acc.x, 16);
    acc.y += __shfl_xor_sync(0xffffffffu, acc.y, 16);
    acc.z += __shfl_xor_sync(0xffffffffu, acc.z, 16);
    acc.w += __shfl_xor_sync(0xffffffffu, acc.w, 16);
    // lanes 0-15 (and mirrored 16-31) now hold y[gw][l15*4 .. l15*4+3]

    if (store_y && half == 0)
        ((float4*)yout)[gw * 16 + l15] = acc;
    if (clear && lane == 0) g_cnt[gw] = 0;                  // reset for next replay

    // fused gated-sum: dot(y, Wg) via 16-lane reduce (both halves compute)
    float4 wg = ((const float4*)Wg)[l15];
    float part = acc.x * wg.x + acc.y * wg.y + acc.z * wg.z + acc.w * wg.w;
#pragma unroll
    for (int o = 8; o; o >>= 1) part += __shfl_xor_sync(0xffffffffu, part, o);
    float gsc = 1.f / (1.f + __expf(-(part + bg[0])));
    if (half == 0) {
        float4* o4 = (float4*)out;
        float4 cur = o4[gw * 16 + l15];
        cur.x += gsc * acc.x; cur.y += gsc * acc.y;
        cur.z += gsc * acc.z; cur.w += gsc * acc.w;
        o4[gw * 16 + l15] = cur;
    }
}

// ---------------- launch -----------------------------------------------------
extern "C" void kernel_launch(void* const* d_in, const int* in_sizes, int n_in,
                              void* d_out, int out_size) {
    const float* X   = (const float*)d_in[0];
    const float* ew  = (const float*)d_in[1];
    const float* W1  = (const float*)d_in[2];
    const float* b1  = (const float*)d_in[3];
    const float* W2  = (const float*)d_in[4];
    const float* b2  = (const float*)d_in[5];
    const float* Wg  = (const float*)d_in[6];
    const float* bg  = (const float*)d_in[7];
    const int*   snd = (const int*)d_in[8];
    const int*   rcv = (const int*)d_in[9];
    float* out = (float*)d_out;

    void* p;
    cudaGetSymbolAddress(&p, g_xL); float* xL = (float*)p;
    cudaGetSymbolAddress(&p, g_xA); float* xA = (float*)p;
    cudaGetSymbolAddress(&p, g_xB); float* xB = (float*)p;

    // launch 1: fused MLP + hop-0 gate (independent of CSR)
    k_mlp<<<(NN + 127) / 128, 256>>>(X, W1, b1, W2, b2, Wg, bg, xL, out, NN);

    // launch 2: bucketed scatter (g_cnt zero on entry; last hop self-clears)
    k_scatter<<<(NE + 255) / 256, 256>>>(snd, rcv, ew);

    // launches 3..22: 20 propagations; launch 4 = hop 2 (steady state, profiled)
    float* bufs[2] = {xA, xB};
    const float* xin = xL;
    for (int k = 0; k < KHOPS; ++k) {
        float* yout = bufs[k & 1];
        int store  = (k < KHOPS - 1) ? 1 : 0;
        int clear  = (k == KHOPS - 1) ? 1 : 0;
        k_spmm_gate<<<NN / 8, 256>>>(xin, yout, store, clear, Wg, bg, out);
        xin = yout;
    }
}